// round 8
// baseline (speedup 1.0000x reference)
#include <cuda_runtime.h>
#include <math.h>
#include <stdint.h>

#define CB   1024
#define BB   4
#define NN   2048
#define HH   16
#define MTOK (BB*NN)   // 8192

// ---------------- scratch (device globals; allocation-free) ----------------
__device__ float g_h   [MTOK * CB];        // LN1 out (tf32-rounded)
__device__ float g_qkv [MTOK * 3 * CB];    // qkv (tf32-rounded)
__device__ float g_att [MTOK * CB];        // attention out (tf32-rounded)
__device__ float g_x2  [MTOK * CB];        // x + proj (full fp32)
__device__ float g_h2  [MTOK * CB];        // LN2 out (tf32-rounded)
__device__ float g_ff  [MTOK * 4 * CB];    // gelu(h2@W1) (tf32-rounded)
__device__ float g_wqkvT [3 * CB * CB];    // transposed + tf32-rounded weights [N,K]
__device__ float g_wprojT[CB * CB];
__device__ float g_w1T   [4 * CB * CB];
__device__ float g_w2T   [4 * CB * CB];

// ---------------- helpers ----------------
__device__ __forceinline__ uint32_t smem_u32(const void* p) {
    uint32_t a;
    asm("{ .reg .u64 t; cvta.to.shared.u64 t, %1; cvt.u32.u64 %0, t; }"
        : "=r"(a) : "l"(p));
    return a;
}
__device__ __forceinline__ float tf32_rnd(float x) {
    uint32_t u;
    asm("cvt.rna.tf32.f32 %0, %1;" : "=r"(u) : "f"(x));
    return __uint_as_float(u);
}
__device__ __forceinline__ void cp_async16(uint32_t d, const void* g) {
    asm volatile("cp.async.cg.shared.global [%0], [%1], 16;" :: "r"(d), "l"(g));
}
#define CP_COMMIT()  asm volatile("cp.async.commit_group;" ::: "memory")
#define CP_WAIT(n)   asm volatile("cp.async.wait_group %0;" :: "n"(n) : "memory")

#define LDMATRIX_X4(r0, r1, r2, r3, addr) \
    asm volatile("ldmatrix.sync.aligned.m8n8.x4.shared.b16 {%0,%1,%2,%3}, [%4];" \
        : "=r"(r0), "=r"(r1), "=r"(r2), "=r"(r3) : "r"(addr))

#define MMA_TF32(c, a, br0, br1) \
    asm volatile("mma.sync.aligned.m16n8k8.row.col.f32.tf32.tf32.f32 " \
        "{%0,%1,%2,%3}, {%4,%5,%6,%7}, {%8,%9}, {%0,%1,%2,%3};" \
        : "+f"((c)[0]), "+f"((c)[1]), "+f"((c)[2]), "+f"((c)[3]) \
        : "r"((a)[0]), "r"((a)[1]), "r"((a)[2]), "r"((a)[3]), "r"(br0), "r"(br1))

// ---------------- LayerNorm (output tf32-rounded) ----------------
__global__ __launch_bounds__(256) void ln_kernel(
    const float* __restrict__ x, const float* __restrict__ g,
    const float* __restrict__ b, float* __restrict__ out)
{
    int row = blockIdx.x;
    int t = threadIdx.x;
    const float4* xr = reinterpret_cast<const float4*>(x + (size_t)row * CB);
    float4 v = xr[t];
    float s  = v.x + v.y + v.z + v.w;
    float ss = v.x*v.x + v.y*v.y + v.z*v.z + v.w*v.w;

    __shared__ float rs_[8], rss_[8];
    __shared__ float mean_s, inv_s;
    #pragma unroll
    for (int o = 16; o > 0; o >>= 1) {
        s  += __shfl_down_sync(0xffffffffu, s,  o);
        ss += __shfl_down_sync(0xffffffffu, ss, o);
    }
    int w = t >> 5, l = t & 31;
    if (l == 0) { rs_[w] = s; rss_[w] = ss; }
    __syncthreads();
    if (t == 0) {
        float S = 0.f, SS = 0.f;
        #pragma unroll
        for (int i = 0; i < 8; i++) { S += rs_[i]; SS += rss_[i]; }
        float mean = S * (1.0f / CB);
        float var  = SS * (1.0f / CB) - mean * mean;
        mean_s = mean;
        inv_s  = rsqrtf(var + 1e-5f);
    }
    __syncthreads();
    float mean = mean_s, inv = inv_s;
    float4 gv = reinterpret_cast<const float4*>(g)[t];
    float4 bv = reinterpret_cast<const float4*>(b)[t];
    float4 o4;
    o4.x = tf32_rnd((v.x - mean) * inv * gv.x + bv.x);
    o4.y = tf32_rnd((v.y - mean) * inv * gv.y + bv.y);
    o4.z = tf32_rnd((v.z - mean) * inv * gv.z + bv.z);
    o4.w = tf32_rnd((v.w - mean) * inv * gv.w + bv.w);
    reinterpret_cast<float4*>(out + (size_t)row * CB)[t] = o4;
}

// ---------------- transpose + tf32 round: Wt[n,k] = rnd(W[k,n]) ----------------
__global__ __launch_bounds__(256) void transpose_rnd_kernel(
    const float* __restrict__ W, float* __restrict__ Wt, int K, int Nc)
{
    __shared__ float t[32][33];
    int n0 = blockIdx.x * 32, k0 = blockIdx.y * 32;
    int tx = threadIdx.x & 31, ty = threadIdx.x >> 5;
    #pragma unroll
    for (int i = 0; i < 32; i += 8)
        t[ty + i][tx] = W[(size_t)(k0 + ty + i) * Nc + n0 + tx];
    __syncthreads();
    #pragma unroll
    for (int i = 0; i < 32; i += 8)
        Wt[(size_t)(n0 + ty + i) * K + k0 + tx] = tf32_rnd(t[tx][ty + i]);
}

// ---------------- mma.sync tf32 GEMM: C[M,Nc] = A[M,K] @ Bt[Nc,K]^T ----------------
// CTA 128x128, K-chunk 32, 3-stage cp.async ring (one barrier per k-tile).
#define GSTAGE 32768                  // A 16KB + B 16KB
#define GSMEM  (3 * GSTAGE)           // 98304

__device__ __forceinline__ float gelu_exact(float v) {
    return 0.5f * v * (1.0f + erff(v * 0.7071067811865476f));
}

__device__ __forceinline__ void gemm_stage_cp(
    uint32_t abase, const float* __restrict__ Ag, const float* __restrict__ Bg,
    int K, int k0, int ldRow, int ldC4)
{
    #pragma unroll
    for (int i = 0; i < 4; i++) {
        int row = ldRow + i * 32;
        uint32_t off = (uint32_t)(row * 128 + ldC4 * 4);
        cp_async16(abase + (off ^ ((off >> 3) & 0x70)),
                   Ag + (size_t)row * K + k0 + ldC4);
    }
    uint32_t bbase = abase + 16384;
    #pragma unroll
    for (int i = 0; i < 4; i++) {
        int row = ldRow + i * 32;
        uint32_t off = (uint32_t)(row * 128 + ldC4 * 4);
        cp_async16(bbase + (off ^ ((off >> 3) & 0x70)),
                   Bg + (size_t)row * K + k0 + ldC4);
    }
    CP_COMMIT();
}

template<bool GELU, bool RES, bool RND>
__global__ __launch_bounds__(256, 2)
void mma_gemm(const float* __restrict__ A, const float* __restrict__ Bt,
              const float* __restrict__ bias, const float* __restrict__ res,
              float* __restrict__ C, int M, int Nc, int K)
{
    extern __shared__ char smem[];
    uint32_t smem_base = smem_u32(smem);
    const int tid  = threadIdx.x;
    const int lane = tid & 31, wid = tid >> 5;
    const int wm = wid & 3, wn = wid >> 2;
    const int bm = blockIdx.y, bn = blockIdx.x;

    const float* Ag = A  + (size_t)(bm * 128) * K;
    const float* Bg = Bt + (size_t)(bn * 128) * K;

    const int ldRow = tid >> 3;
    const int ldC4  = (tid & 7) * 4;

    float acc[2][8][4];
    #pragma unroll
    for (int t = 0; t < 2; t++)
        #pragma unroll
        for (int u = 0; u < 8; u++)
            #pragma unroll
            for (int q = 0; q < 4; q++) acc[t][u][q] = 0.f;

    const int fr  = ((lane >> 3) & 1) * 8 + (lane & 7);
    const int fks = (lane >> 4);

    const int nkt = K >> 5;
    // prologue: stages 0,1 in flight
    gemm_stage_cp(smem_base,          Ag, Bg, K, 0,  ldRow, ldC4);
    gemm_stage_cp(smem_base + GSTAGE, Ag, Bg, K, 32, ldRow, ldC4);

    int buf = 0, pbuf = 2;
    for (int kt = 0; kt < nkt; kt++) {
        CP_WAIT(1);            // stage kt resident
        __syncthreads();       // all warps done with stage kt-1 compute (frees pbuf)
        if (kt + 2 < nkt)
            gemm_stage_cp(smem_base + pbuf * GSTAGE, Ag, Bg, K, (kt + 2) * 32, ldRow, ldC4);
        else
            CP_COMMIT();       // empty group keeps CP_WAIT(1) == "stage kt+1 done"

        uint32_t ab = smem_base + buf * GSTAGE;
        uint32_t bb = ab + 16384;

        #pragma unroll
        for (int ks = 0; ks < 4; ks++) {
            uint32_t afr[2][4], bfr[4][4];
            #pragma unroll
            for (int t = 0; t < 2; t++) {
                int arow = wm * 32 + t * 16 + fr;
                int acol = (ks * 2 + fks) ^ (arow & 7);
                uint32_t aaddr = ab + arow * 128 + acol * 16;
                LDMATRIX_X4(afr[t][0], afr[t][1], afr[t][2], afr[t][3], aaddr);
            }
            #pragma unroll
            for (int p = 0; p < 4; p++) {
                int brow = wn * 64 + p * 16 + fr;
                int bcol = (ks * 2 + fks) ^ (brow & 7);
                uint32_t baddr = bb + brow * 128 + bcol * 16;
                LDMATRIX_X4(bfr[p][0], bfr[p][1], bfr[p][2], bfr[p][3], baddr);
            }
            #pragma unroll
            for (int t = 0; t < 2; t++)
                #pragma unroll
                for (int u = 0; u < 8; u++)
                    MMA_TF32(acc[t][u], afr[t], bfr[u >> 1][u & 1], bfr[u >> 1][2 + (u & 1)]);
        }
        buf  = (buf == 2)  ? 0 : buf + 1;
        pbuf = (pbuf == 2) ? 0 : pbuf + 1;
    }

    const int r0 = bm * 128 + wm * 32 + (lane >> 2);
    const int cb0 = bn * 128 + wn * 64 + (lane & 3) * 2;
    #pragma unroll
    for (int t = 0; t < 2; t++) {
        int gr = r0 + t * 16;
        #pragma unroll
        for (int u = 0; u < 8; u++) {
            int gc = cb0 + u * 8;
            float2 bv = *reinterpret_cast<const float2*>(bias + gc);
            float v0 = acc[t][u][0] + bv.x;
            float v1 = acc[t][u][1] + bv.y;
            float v2 = acc[t][u][2] + bv.x;
            float v3 = acc[t][u][3] + bv.y;
            if (GELU) {
                v0 = gelu_exact(v0); v1 = gelu_exact(v1);
                v2 = gelu_exact(v2); v3 = gelu_exact(v3);
            }
            size_t o1 = (size_t)gr * Nc + gc;
            size_t o2 = (size_t)(gr + 8) * Nc + gc;
            if (RES) {
                float2 r1 = *reinterpret_cast<const float2*>(res + o1);
                float2 r2 = *reinterpret_cast<const float2*>(res + o2);
                v0 += r1.x; v1 += r1.y; v2 += r2.x; v3 += r2.y;
            }
            if (RND) {
                v0 = tf32_rnd(v0); v1 = tf32_rnd(v1);
                v2 = tf32_rnd(v2); v3 = tf32_rnd(v3);
            }
            *reinterpret_cast<float2*>(C + o1) = make_float2(v0, v1);
            *reinterpret_cast<float2*>(C + o2) = make_float2(v2, v3);
        }
    }
}

// ---------------- tensor-core flash attention ----------------
// CTA: 128 queries x one (b,h). 8 warps x 16 query rows. KV tile 64.
#define QST 68
#define ATT_SMEM ((128 + 64 + 64) * QST * 4)   // 69632

__global__ __launch_bounds__(256) void attn_mma_kernel(
    const float* __restrict__ qkv, float* __restrict__ out)
{
    extern __shared__ float sm[];
    float* Qs = sm;                 // [128][QST]
    float* Ks = sm + 128 * QST;     // [64][QST]
    float* Vt = Ks + 64 * QST;      // [64 d][QST] (kv xor-swizzled)

    const int tid = threadIdx.x;
    const int lane = tid & 31, wid = tid >> 5;
    const int b = blockIdx.y >> 4, h = blockIdx.y & 15;
    const int q0 = blockIdx.x * 128;

    const float* qbase = qkv + ((size_t)(b * NN + q0)) * (3 * CB) + h * 64;

    // load Q tile [128][64]
    {
        int row = tid >> 1, cb = (tid & 1) * 32;
        #pragma unroll
        for (int i = 0; i < 8; i++) {
            float4 v = *reinterpret_cast<const float4*>(qbase + (size_t)row * (3 * CB) + cb + 4 * i);
            *reinterpret_cast<float4*>(Qs + row * QST + cb + 4 * i) = v;
        }
    }
    __syncthreads();

    const int fr  = ((lane >> 3) & 1) * 8 + (lane & 7);
    const int fks = lane >> 4;
    const uint32_t ks_u = smem_u32(Ks), vt_u = smem_u32(Vt);

    // Q fragments resident in registers
    uint32_t qf[8][4];
    {
        uint32_t qrow_addr = smem_u32(Qs) + (wid * 16 + fr) * (QST * 4);
        #pragma unroll
        for (int ks = 0; ks < 8; ks++)
            LDMATRIX_X4(qf[ks][0], qf[ks][1], qf[ks][2], qf[ks][3],
                        qrow_addr + (ks * 2 + fks) * 16);
    }

    float oacc[8][4];
    #pragma unroll
    for (int u = 0; u < 8; u++)
        #pragma unroll
        for (int q = 0; q < 4; q++) oacc[u][q] = 0.f;
    float m0 = -1e30f, m1 = -1e30f, l0 = 0.f, l1 = 0.f;

    const int srcA = (lane & ~3) | ((lane & 3) >> 1);
    const int srcB = srcA + 2;
    const int psel = lane & 1;

    for (int j0 = 0; j0 < NN; j0 += 64) {
        const float* kbase = qkv + ((size_t)(b * NN + j0)) * (3 * CB) + CB + h * 64;
        const float* vbase = kbase + CB;
        __syncthreads();
        {
            int krow = tid >> 2, kcb = (tid & 3) * 16;
            #pragma unroll
            for (int i = 0; i < 4; i++) {
                float4 v = *reinterpret_cast<const float4*>(kbase + (size_t)krow * (3 * CB) + kcb + 4 * i);
                *reinterpret_cast<float4*>(Ks + krow * QST + kcb + 4 * i) = v;
            }
            int vkv = (tid >> 5) * 8 + (lane >> 2);
            int dbase = (lane & 3) * 16;
            int kvx = vkv ^ ((lane & 3) * 8);
            #pragma unroll
            for (int i = 0; i < 4; i++) {
                float4 v = *reinterpret_cast<const float4*>(vbase + (size_t)vkv * (3 * CB) + dbase + 4 * i);
                int d = dbase + 4 * i;
                Vt[(d + 0) * QST + kvx] = v.x;
                Vt[(d + 1) * QST + kvx] = v.y;
                Vt[(d + 2) * QST + kvx] = v.z;
                Vt[(d + 3) * QST + kvx] = v.w;
            }
        }
        __syncthreads();

        // S = Q @ K^T
        float sacc[8][4];
        #pragma unroll
        for (int u = 0; u < 8; u++)
            #pragma unroll
            for (int q = 0; q < 4; q++) sacc[u][q] = 0.f;
        #pragma unroll
        for (int ks = 0; ks < 8; ks++) {
            uint32_t bf[4][4];
            #pragma unroll
            for (int u2 = 0; u2 < 4; u2++)
                LDMATRIX_X4(bf[u2][0], bf[u2][1], bf[u2][2], bf[u2][3],
                            ks_u + (u2 * 16 + fr) * (QST * 4) + (ks * 2 + fks) * 16);
            #pragma unroll
            for (int u = 0; u < 8; u++)
                MMA_TF32(sacc[u], qf[ks], bf[u >> 1][u & 1], bf[u >> 1][2 + (u & 1)]);
        }

        // online softmax
        float mx0 = -1e30f, mx1 = -1e30f;
        #pragma unroll
        for (int u = 0; u < 8; u++) {
            sacc[u][0] *= 0.125f; sacc[u][1] *= 0.125f;
            sacc[u][2] *= 0.125f; sacc[u][3] *= 0.125f;
            mx0 = fmaxf(mx0, fmaxf(sacc[u][0], sacc[u][1]));
            mx1 = fmaxf(mx1, fmaxf(sacc[u][2], sacc[u][3]));
        }
        mx0 = fmaxf(mx0, __shfl_xor_sync(0xffffffffu, mx0, 1));
        mx0 = fmaxf(mx0, __shfl_xor_sync(0xffffffffu, mx0, 2));
        mx1 = fmaxf(mx1, __shfl_xor_sync(0xffffffffu, mx1, 1));
        mx1 = fmaxf(mx1, __shfl_xor_sync(0xffffffffu, mx1, 2));
        float nm0 = fmaxf(m0, mx0), nm1 = fmaxf(m1, mx1);
        float corr0 = __expf(m0 - nm0), corr1 = __expf(m1 - nm1);
        float rs0 = 0.f, rs1 = 0.f;
        #pragma unroll
        for (int u = 0; u < 8; u++) {
            sacc[u][0] = __expf(sacc[u][0] - nm0); rs0 += sacc[u][0];
            sacc[u][1] = __expf(sacc[u][1] - nm0); rs0 += sacc[u][1];
            sacc[u][2] = __expf(sacc[u][2] - nm1); rs1 += sacc[u][2];
            sacc[u][3] = __expf(sacc[u][3] - nm1); rs1 += sacc[u][3];
        }
        rs0 += __shfl_xor_sync(0xffffffffu, rs0, 1);
        rs0 += __shfl_xor_sync(0xffffffffu, rs0, 2);
        rs1 += __shfl_xor_sync(0xffffffffu, rs1, 1);
        rs1 += __shfl_xor_sync(0xffffffffu, rs1, 2);
        l0 = l0 * corr0 + rs0; m0 = nm0;
        l1 = l1 * corr1 + rs1; m1 = nm1;
        #pragma unroll
        for (int u = 0; u < 8; u++) {
            oacc[u][0] *= corr0; oacc[u][1] *= corr0;
            oacc[u][2] *= corr1; oacc[u][3] *= corr1;
        }

        // O += P @ V
        #pragma unroll
        for (int ks = 0; ks < 8; ks++) {
            float x0 = __shfl_sync(0xffffffffu, sacc[ks][0], srcA);
            float x1 = __shfl_sync(0xffffffffu, sacc[ks][1], srcA);
            float y0 = __shfl_sync(0xffffffffu, sacc[ks][2], srcA);
            float y1 = __shfl_sync(0xffffffffu, sacc[ks][3], srcA);
            float z0 = __shfl_sync(0xffffffffu, sacc[ks][0], srcB);
            float z1 = __shfl_sync(0xffffffffu, sacc[ks][1], srcB);
            float w0 = __shfl_sync(0xffffffffu, sacc[ks][2], srcB);
            float w1 = __shfl_sync(0xffffffffu, sacc[ks][3], srcB);
            uint32_t af[4];
            af[0] = __float_as_uint(tf32_rnd(psel ? x1 : x0));
            af[1] = __float_as_uint(tf32_rnd(psel ? y1 : y0));
            af[2] = __float_as_uint(tf32_rnd(psel ? z1 : z0));
            af[3] = __float_as_uint(tf32_rnd(psel ? w1 : w0));
            uint32_t bf[4][4];
            #pragma unroll
            for (int u2 = 0; u2 < 4; u2++)
                LDMATRIX_X4(bf[u2][0], bf[u2][1], bf[u2][2], bf[u2][3],
                            vt_u + (u2 * 16 + fr) * (QST * 4) +
                            (((ks * 2 + fks) ^ (2 * u2)) * 16));
            #pragma unroll
            for (int u = 0; u < 8; u++)
                MMA_TF32(oacc[u], af, bf[u >> 1][u & 1], bf[u >> 1][2 + (u & 1)]);
        }
    }

    float inv0 = 1.0f / l0, inv1 = 1.0f / l1;
    int qrow = q0 + wid * 16 + (lane >> 2);
    float* ob  = out + ((size_t)(b * NN + qrow)) * CB + h * 64 + (lane & 3) * 2;
    float* ob2 = ob + 8 * CB;
    #pragma unroll
    for (int u = 0; u < 8; u++) {
        *reinterpret_cast<float2*>(ob + u * 8) =
            make_float2(tf32_rnd(oacc[u][0] * inv0), tf32_rnd(oacc[u][1] * inv0));
        *reinterpret_cast<float2*>(ob2 + u * 8) =
            make_float2(tf32_rnd(oacc[u][2] * inv1), tf32_rnd(oacc[u][3] * inv1));
    }
}

// ---------------- launch ----------------
extern "C" void kernel_launch(void* const* d_in, const int* in_sizes, int n_in,
                              void* d_out, int out_size)
{
    const float* x     = (const float*)d_in[0];
    const float* Wqkv  = (const float*)d_in[1];
    const float* bqkv  = (const float*)d_in[2];
    const float* Wproj = (const float*)d_in[3];
    const float* bproj = (const float*)d_in[4];
    const float* g1    = (const float*)d_in[5];
    const float* b1    = (const float*)d_in[6];
    const float* g2    = (const float*)d_in[7];
    const float* b2    = (const float*)d_in[8];
    const float* W1    = (const float*)d_in[9];
    const float* bf1   = (const float*)d_in[10];
    const float* W2    = (const float*)d_in[11];
    const float* bf2   = (const float*)d_in[12];
    float* out = (float*)d_out;

    float *hbuf, *qkvbuf, *attbuf, *x2buf, *h2buf, *ffbuf;
    float *wqkvT, *wprojT, *w1T, *w2T;
    cudaGetSymbolAddress((void**)&hbuf,   g_h);
    cudaGetSymbolAddress((void**)&qkvbuf, g_qkv);
    cudaGetSymbolAddress((void**)&attbuf, g_att);
    cudaGetSymbolAddress((void**)&x2buf,  g_x2);
    cudaGetSymbolAddress((void**)&h2buf,  g_h2);
    cudaGetSymbolAddress((void**)&ffbuf,  g_ff);
    cudaGetSymbolAddress((void**)&wqkvT,  g_wqkvT);
    cudaGetSymbolAddress((void**)&wprojT, g_wprojT);
    cudaGetSymbolAddress((void**)&w1T,    g_w1T);
    cudaGetSymbolAddress((void**)&w2T,    g_w2T);

    cudaFuncSetAttribute(attn_mma_kernel, cudaFuncAttributeMaxDynamicSharedMemorySize, ATT_SMEM);
    cudaFuncSetAttribute(mma_gemm<false, false, true >, cudaFuncAttributeMaxDynamicSharedMemorySize, GSMEM);
    cudaFuncSetAttribute(mma_gemm<false, true,  false>, cudaFuncAttributeMaxDynamicSharedMemorySize, GSMEM);
    cudaFuncSetAttribute(mma_gemm<true,  false, true >, cudaFuncAttributeMaxDynamicSharedMemorySize, GSMEM);

    // weight transposes (+tf32 round)
    transpose_rnd_kernel<<<dim3(3 * CB / 32, CB / 32), 256>>>(Wqkv,  wqkvT,  CB, 3 * CB);
    transpose_rnd_kernel<<<dim3(CB / 32, CB / 32), 256>>>(Wproj, wprojT, CB, CB);
    transpose_rnd_kernel<<<dim3(4 * CB / 32, CB / 32), 256>>>(W1, w1T, CB, 4 * CB);
    transpose_rnd_kernel<<<dim3(CB / 32, 4 * CB / 32), 256>>>(W2, w2T, 4 * CB, CB);

    // 1. LN1 (rounded)
    ln_kernel<<<MTOK, 256>>>(x, g1, b1, hbuf);
    // 2. qkv = round(h @ Wqkv + bqkv)
    mma_gemm<false, false, true><<<dim3(3 * CB / 128, MTOK / 128), 256, GSMEM>>>(
        hbuf, wqkvT, bqkv, nullptr, qkvbuf, MTOK, 3 * CB, CB);
    // 3. attention (tensor core, output rounded)
    attn_mma_kernel<<<dim3(NN / 128, BB * HH), 256, ATT_SMEM>>>(qkvbuf, attbuf);
    // 4. x2 = att @ Wproj + bproj + x
    mma_gemm<false, true, false><<<dim3(CB / 128, MTOK / 128), 256, GSMEM>>>(
        attbuf, wprojT, bproj, x, x2buf, MTOK, CB, CB);
    // 5. LN2 (rounded)
    ln_kernel<<<MTOK, 256>>>(x2buf, g2, b2, h2buf);
    // 6. ff = round(gelu(h2 @ W1 + bf1))
    mma_gemm<true, false, true><<<dim3(4 * CB / 128, MTOK / 128), 256, GSMEM>>>(
        h2buf, w1T, bf1, nullptr, ffbuf, MTOK, 4 * CB, CB);
    // 7. out = ff @ W2 + bf2 + x2
    mma_gemm<false, true, false><<<dim3(CB / 128, MTOK / 128), 256, GSMEM>>>(
        ffbuf, w2T, bf2, x2buf, out, MTOK, CB, 4 * CB);
}

// round 9
// speedup vs baseline: 1.9496x; 1.9496x over previous
#include <cuda_runtime.h>
#include <cuda_fp16.h>
#include <math.h>
#include <stdint.h>

#define CB   1024
#define BB   4
#define NN   2048
#define HH   16
#define MTOK (BB*NN)   // 8192

// ---------------- scratch (device globals; allocation-free) ----------------
__device__ __half g_h   [MTOK * CB];        // LN1 out (fp16)
__device__ __half g_qkv [MTOK * 3 * CB];    // qkv (fp16)
__device__ __half g_att [MTOK * CB];        // attention out (fp16)
__device__ float  g_x2  [MTOK * CB];        // x + proj (full fp32)
__device__ __half g_h2  [MTOK * CB];        // LN2 out (fp16)
__device__ __half g_ff  [MTOK * 4 * CB];    // gelu(h2@W1) (fp16)
__device__ __half g_wqkvT [3 * CB * CB];    // transposed fp16 weights [N,K]
__device__ __half g_wprojT[CB * CB];
__device__ __half g_w1T   [4 * CB * CB];
__device__ __half g_w2T   [4 * CB * CB];

// ---------------- helpers ----------------
__device__ __forceinline__ uint32_t smem_u32(const void* p) {
    uint32_t a;
    asm("{ .reg .u64 t; cvta.to.shared.u64 t, %1; cvt.u32.u64 %0, t; }"
        : "=r"(a) : "l"(p));
    return a;
}
__device__ __forceinline__ uint32_t pack_h2(float a, float b) {
    __half2 h = __floats2half2_rn(a, b);
    return *reinterpret_cast<uint32_t*>(&h);
}
__device__ __forceinline__ void cp_async16(uint32_t d, const void* g) {
    asm volatile("cp.async.cg.shared.global [%0], [%1], 16;" :: "r"(d), "l"(g));
}
#define CP_COMMIT()  asm volatile("cp.async.commit_group;" ::: "memory")
#define CP_WAIT(n)   asm volatile("cp.async.wait_group %0;" :: "n"(n) : "memory")

#define LDMATRIX_X4(r0, r1, r2, r3, addr) \
    asm volatile("ldmatrix.sync.aligned.m8n8.x4.shared.b16 {%0,%1,%2,%3}, [%4];" \
        : "=r"(r0), "=r"(r1), "=r"(r2), "=r"(r3) : "r"(addr))

#define LDMATRIX_X4_T(r0, r1, r2, r3, addr) \
    asm volatile("ldmatrix.sync.aligned.m8n8.x4.trans.shared.b16 {%0,%1,%2,%3}, [%4];" \
        : "=r"(r0), "=r"(r1), "=r"(r2), "=r"(r3) : "r"(addr))

#define MMA_F16(c, a, b0, b1) \
    asm volatile("mma.sync.aligned.m16n8k16.row.col.f32.f16.f16.f32 " \
        "{%0,%1,%2,%3}, {%4,%5,%6,%7}, {%8,%9}, {%0,%1,%2,%3};" \
        : "+f"((c)[0]), "+f"((c)[1]), "+f"((c)[2]), "+f"((c)[3]) \
        : "r"((a)[0]), "r"((a)[1]), "r"((a)[2]), "r"((a)[3]), "r"(b0), "r"(b1))

// 64B-row swizzle: chunk' = chunk ^ ((row>>1)&3)  (conflict-free ldmatrix + stores)
#define SW64(o) ((o) ^ (((o) >> 3) & 0x30))

// ---------------- LayerNorm: fp32 in -> fp16 out ----------------
__global__ __launch_bounds__(256) void ln_kernel(
    const float* __restrict__ x, const float* __restrict__ g,
    const float* __restrict__ b, __half* __restrict__ out)
{
    int row = blockIdx.x;
    int t = threadIdx.x;
    const float4* xr = reinterpret_cast<const float4*>(x + (size_t)row * CB);
    float4 v = xr[t];
    float s  = v.x + v.y + v.z + v.w;
    float ss = v.x*v.x + v.y*v.y + v.z*v.z + v.w*v.w;

    __shared__ float rs_[8], rss_[8];
    __shared__ float mean_s, inv_s;
    #pragma unroll
    for (int o = 16; o > 0; o >>= 1) {
        s  += __shfl_down_sync(0xffffffffu, s,  o);
        ss += __shfl_down_sync(0xffffffffu, ss, o);
    }
    int w = t >> 5, l = t & 31;
    if (l == 0) { rs_[w] = s; rss_[w] = ss; }
    __syncthreads();
    if (t == 0) {
        float S = 0.f, SS = 0.f;
        #pragma unroll
        for (int i = 0; i < 8; i++) { S += rs_[i]; SS += rss_[i]; }
        float mean = S * (1.0f / CB);
        float var  = SS * (1.0f / CB) - mean * mean;
        mean_s = mean;
        inv_s  = rsqrtf(var + 1e-5f);
    }
    __syncthreads();
    float mean = mean_s, inv = inv_s;
    float4 gv = reinterpret_cast<const float4*>(g)[t];
    float4 bv = reinterpret_cast<const float4*>(b)[t];
    uint2 o2;
    o2.x = pack_h2((v.x - mean) * inv * gv.x + bv.x, (v.y - mean) * inv * gv.y + bv.y);
    o2.y = pack_h2((v.z - mean) * inv * gv.z + bv.z, (v.w - mean) * inv * gv.w + bv.w);
    *reinterpret_cast<uint2*>(out + (size_t)row * CB + t * 4) = o2;
}

// ---------------- transpose + fp16: Wt[n,k] = h(W[k,n]) ----------------
__global__ __launch_bounds__(256) void transpose_h_kernel(
    const float* __restrict__ W, __half* __restrict__ Wt, int K, int Nc)
{
    __shared__ float t[32][33];
    int n0 = blockIdx.x * 32, k0 = blockIdx.y * 32;
    int tx = threadIdx.x & 31, ty = threadIdx.x >> 5;
    #pragma unroll
    for (int i = 0; i < 32; i += 8)
        t[ty + i][tx] = W[(size_t)(k0 + ty + i) * Nc + n0 + tx];
    __syncthreads();
    #pragma unroll
    for (int i = 0; i < 32; i += 8)
        Wt[(size_t)(n0 + ty + i) * K + k0 + tx] = __float2half_rn(t[tx][ty + i]);
}

// ---------------- fp16 mma GEMM: C[M,Nc] = A[M,K] @ Bt[Nc,K]^T ----------------
// CTA 128x128, K-chunk 32 (64B rows), 3-stage cp.async ring.
#define GSTAGE 16384                  // A 8KB + B 8KB
#define GSMEM  (3 * GSTAGE)           // 49152

__device__ __forceinline__ float gelu_exact(float v) {
    return 0.5f * v * (1.0f + erff(v * 0.7071067811865476f));
}

__device__ __forceinline__ void gemm_stage_cp(
    uint32_t abase, const __half* __restrict__ Ag, const __half* __restrict__ Bg,
    int K, int k0, int ldRow, int ldC)
{
    // A tile: 128 rows x 64B (4 chunks/row); 256 thr -> 2 rows each
    #pragma unroll
    for (int i = 0; i < 2; i++) {
        int row = ldRow + i * 64;
        uint32_t off = (uint32_t)(row * 64 + ldC * 16);
        cp_async16(abase + SW64(off), Ag + (size_t)row * K + k0 + ldC * 8);
    }
    uint32_t bbase = abase + 8192;
    #pragma unroll
    for (int i = 0; i < 2; i++) {
        int row = ldRow + i * 64;
        uint32_t off = (uint32_t)(row * 64 + ldC * 16);
        cp_async16(bbase + SW64(off), Bg + (size_t)row * K + k0 + ldC * 8);
    }
    CP_COMMIT();
}

template<bool GELU, bool RES, typename OutT>
__global__ __launch_bounds__(256, 2)
void mma_gemm(const __half* __restrict__ A, const __half* __restrict__ Bt,
              const float* __restrict__ bias, const float* __restrict__ res,
              OutT* __restrict__ C, int M, int Nc, int K)
{
    extern __shared__ char smem[];
    uint32_t smem_base = smem_u32(smem);
    const int tid  = threadIdx.x;
    const int lane = tid & 31, wid = tid >> 5;
    const int wm = wid & 3, wn = wid >> 2;
    const int bm = blockIdx.y, bn = blockIdx.x;

    const __half* Ag = A  + (size_t)(bm * 128) * K;
    const __half* Bg = Bt + (size_t)(bn * 128) * K;

    const int ldRow = tid >> 2;          // 0..63
    const int ldC   = tid & 3;           // 16B chunk in row

    float acc[2][8][4];
    #pragma unroll
    for (int t = 0; t < 2; t++)
        #pragma unroll
        for (int u = 0; u < 8; u++)
            #pragma unroll
            for (int q = 0; q < 4; q++) acc[t][u][q] = 0.f;

    const int frow  = lane & 15;         // row within 16-tile
    const int fkoff = (lane >> 4) * 16;  // 0 / 16 bytes (k+8)

    const int nkt = K >> 5;
    gemm_stage_cp(smem_base,          Ag, Bg, K, 0,  ldRow, ldC);
    gemm_stage_cp(smem_base + GSTAGE, Ag, Bg, K, 32, ldRow, ldC);

    int buf = 0, pbuf = 2;
    for (int kt = 0; kt < nkt; kt++) {
        CP_WAIT(1);
        __syncthreads();
        if (kt + 2 < nkt)
            gemm_stage_cp(smem_base + pbuf * GSTAGE, Ag, Bg, K, (kt + 2) * 32, ldRow, ldC);
        else
            CP_COMMIT();

        uint32_t ab = smem_base + buf * GSTAGE;
        uint32_t bb = ab + 8192;

        #pragma unroll
        for (int ks = 0; ks < 2; ks++) {
            uint32_t afr[2][4], bfr[4][4];
            int kbyte = ks * 32 + fkoff;
            #pragma unroll
            for (int t = 0; t < 2; t++) {
                uint32_t off = (uint32_t)((wm * 32 + t * 16 + frow) * 64 + kbyte);
                LDMATRIX_X4(afr[t][0], afr[t][1], afr[t][2], afr[t][3], ab + SW64(off));
            }
            #pragma unroll
            for (int p = 0; p < 4; p++) {
                uint32_t off = (uint32_t)((wn * 64 + p * 16 + frow) * 64 + kbyte);
                LDMATRIX_X4(bfr[p][0], bfr[p][1], bfr[p][2], bfr[p][3], bb + SW64(off));
            }
            #pragma unroll
            for (int t = 0; t < 2; t++)
                #pragma unroll
                for (int u = 0; u < 8; u++)
                    MMA_F16(acc[t][u], afr[t], bfr[u >> 1][u & 1], bfr[u >> 1][2 + (u & 1)]);
        }
        buf  = (buf == 2)  ? 0 : buf + 1;
        pbuf = (pbuf == 2) ? 0 : pbuf + 1;
    }

    const int r0 = bm * 128 + wm * 32 + (lane >> 2);
    const int cb0 = bn * 128 + wn * 64 + (lane & 3) * 2;
    #pragma unroll
    for (int t = 0; t < 2; t++) {
        int gr = r0 + t * 16;
        #pragma unroll
        for (int u = 0; u < 8; u++) {
            int gc = cb0 + u * 8;
            float2 bv = *reinterpret_cast<const float2*>(bias + gc);
            float v0 = acc[t][u][0] + bv.x;
            float v1 = acc[t][u][1] + bv.y;
            float v2 = acc[t][u][2] + bv.x;
            float v3 = acc[t][u][3] + bv.y;
            if (GELU) {
                v0 = gelu_exact(v0); v1 = gelu_exact(v1);
                v2 = gelu_exact(v2); v3 = gelu_exact(v3);
            }
            size_t o1 = (size_t)gr * Nc + gc;
            size_t o2 = (size_t)(gr + 8) * Nc + gc;
            if (RES) {
                float2 r1 = *reinterpret_cast<const float2*>(res + o1);
                float2 r2 = *reinterpret_cast<const float2*>(res + o2);
                v0 += r1.x; v1 += r1.y; v2 += r2.x; v3 += r2.y;
            }
            if (sizeof(OutT) == 2) {
                *reinterpret_cast<uint32_t*>((__half*)C + o1) = pack_h2(v0, v1);
                *reinterpret_cast<uint32_t*>((__half*)C + o2) = pack_h2(v2, v3);
            } else {
                *reinterpret_cast<float2*>((float*)C + o1) = make_float2(v0, v1);
                *reinterpret_cast<float2*>((float*)C + o2) = make_float2(v2, v3);
            }
        }
    }
}

// ---------------- fp16 tensor-core flash attention ----------------
// CTA: 128 queries x one (b,h). 8 warps x 16 query rows. KV tile 64.
// Q/K/V smem rows stride 72 halves (144B) -> naturally conflict-free ldmatrix.
#define QST2 72
#define ATT_SMEM ((128 + 64 + 64) * QST2 * 2)   // 36864

__global__ __launch_bounds__(256) void attn_mma_kernel(
    const __half* __restrict__ qkv, __half* __restrict__ out)
{
    extern __shared__ __half smh[];
    __half* Qs = smh;                 // [128][72]
    __half* Ks = smh + 128 * QST2;    // [64][72]
    __half* Vs = Ks + 64 * QST2;      // [64][72]  (V stored [kv][d], trans-ldsm later)

    const int tid = threadIdx.x;
    const int lane = tid & 31, wid = tid >> 5;
    const int b = blockIdx.y >> 4, h = blockIdx.y & 15;
    const int q0 = blockIdx.x * 128;

    const __half* qbase = qkv + ((size_t)(b * NN + q0)) * (3 * CB) + h * 64;

    // load Q tile [128][64]
    #pragma unroll
    for (int i = 0; i < 4; i++) {
        int row = (tid >> 3) + i * 32;
        int c8  = (tid & 7) * 8;
        uint4 v = *reinterpret_cast<const uint4*>(qbase + (size_t)row * (3 * CB) + c8);
        *reinterpret_cast<uint4*>(Qs + row * QST2 + c8) = v;
    }
    __syncthreads();

    const int frow  = lane & 15;
    const int fkoff = (lane >> 4) * 16;
    const uint32_t ks_u = smem_u32(Ks), vs_u = smem_u32(Vs);

    // Q fragments resident: qf[ks16][4]
    uint32_t qf[4][4];
    {
        uint32_t qrow = smem_u32(Qs) + (wid * 16 + frow) * (QST2 * 2);
        #pragma unroll
        for (int ks = 0; ks < 4; ks++)
            LDMATRIX_X4(qf[ks][0], qf[ks][1], qf[ks][2], qf[ks][3],
                        qrow + ks * 32 + fkoff);
    }

    float oacc[8][4];
    #pragma unroll
    for (int u = 0; u < 8; u++)
        #pragma unroll
        for (int q = 0; q < 4; q++) oacc[u][q] = 0.f;
    float m0 = -1e30f, m1 = -1e30f, l0 = 0.f, l1 = 0.f;

    for (int j0 = 0; j0 < NN; j0 += 64) {
        const __half* kbase = qkv + ((size_t)(b * NN + j0)) * (3 * CB) + CB + h * 64;
        const __half* vbase = kbase + CB;
        __syncthreads();
        #pragma unroll
        for (int i = 0; i < 2; i++) {
            int row = (tid >> 3) + i * 32;
            int c8  = (tid & 7) * 8;
            uint4 kv4 = *reinterpret_cast<const uint4*>(kbase + (size_t)row * (3 * CB) + c8);
            *reinterpret_cast<uint4*>(Ks + row * QST2 + c8) = kv4;
            uint4 vv = *reinterpret_cast<const uint4*>(vbase + (size_t)row * (3 * CB) + c8);
            *reinterpret_cast<uint4*>(Vs + row * QST2 + c8) = vv;
        }
        __syncthreads();

        // S = Q @ K^T  (warp 16 x 64, k=64)
        float sacc[8][4];
        #pragma unroll
        for (int u = 0; u < 8; u++)
            #pragma unroll
            for (int q = 0; q < 4; q++) sacc[u][q] = 0.f;
        #pragma unroll
        for (int ks = 0; ks < 4; ks++) {
            uint32_t bf[4][4];
            int kbyte = ks * 32 + fkoff;
            #pragma unroll
            for (int p = 0; p < 4; p++)
                LDMATRIX_X4(bf[p][0], bf[p][1], bf[p][2], bf[p][3],
                            ks_u + (p * 16 + frow) * (QST2 * 2) + kbyte);
            #pragma unroll
            for (int u = 0; u < 8; u++)
                MMA_F16(sacc[u], qf[ks], bf[u >> 1][u & 1], bf[u >> 1][2 + (u & 1)]);
        }

        // online softmax (rows lane>>2 and +8)
        float mx0 = -1e30f, mx1 = -1e30f;
        #pragma unroll
        for (int u = 0; u < 8; u++) {
            sacc[u][0] *= 0.125f; sacc[u][1] *= 0.125f;
            sacc[u][2] *= 0.125f; sacc[u][3] *= 0.125f;
            mx0 = fmaxf(mx0, fmaxf(sacc[u][0], sacc[u][1]));
            mx1 = fmaxf(mx1, fmaxf(sacc[u][2], sacc[u][3]));
        }
        mx0 = fmaxf(mx0, __shfl_xor_sync(0xffffffffu, mx0, 1));
        mx0 = fmaxf(mx0, __shfl_xor_sync(0xffffffffu, mx0, 2));
        mx1 = fmaxf(mx1, __shfl_xor_sync(0xffffffffu, mx1, 1));
        mx1 = fmaxf(mx1, __shfl_xor_sync(0xffffffffu, mx1, 2));
        float nm0 = fmaxf(m0, mx0), nm1 = fmaxf(m1, mx1);
        float corr0 = __expf(m0 - nm0), corr1 = __expf(m1 - nm1);
        float rs0 = 0.f, rs1 = 0.f;
        #pragma unroll
        for (int u = 0; u < 8; u++) {
            sacc[u][0] = __expf(sacc[u][0] - nm0); rs0 += sacc[u][0];
            sacc[u][1] = __expf(sacc[u][1] - nm0); rs0 += sacc[u][1];
            sacc[u][2] = __expf(sacc[u][2] - nm1); rs1 += sacc[u][2];
            sacc[u][3] = __expf(sacc[u][3] - nm1); rs1 += sacc[u][3];
        }
        rs0 += __shfl_xor_sync(0xffffffffu, rs0, 1);
        rs0 += __shfl_xor_sync(0xffffffffu, rs0, 2);
        rs1 += __shfl_xor_sync(0xffffffffu, rs1, 1);
        rs1 += __shfl_xor_sync(0xffffffffu, rs1, 2);
        l0 = l0 * corr0 + rs0; m0 = nm0;
        l1 = l1 * corr1 + rs1; m1 = nm1;
        #pragma unroll
        for (int u = 0; u < 8; u++) {
            oacc[u][0] *= corr0; oacc[u][1] *= corr0;
            oacc[u][2] *= corr1; oacc[u][3] *= corr1;
        }

        // O += P @ V : P A-frags by direct register packing (C-cols == A-k cols)
        #pragma unroll
        for (int j = 0; j < 4; j++) {
            uint32_t af[4];
            af[0] = pack_h2(sacc[2*j][0],   sacc[2*j][1]);
            af[1] = pack_h2(sacc[2*j][2],   sacc[2*j][3]);
            af[2] = pack_h2(sacc[2*j+1][0], sacc[2*j+1][1]);
            af[3] = pack_h2(sacc[2*j+1][2], sacc[2*j+1][3]);
            #pragma unroll
            for (int p = 0; p < 4; p++) {
                uint32_t vf[4];
                int kvrow = j * 16 + ((lane >> 4) ? 8 : 0) + (lane & 7);
                int dbyte = p * 32 + ((lane >> 3) & 1) * 16;
                LDMATRIX_X4_T(vf[0], vf[1], vf[2], vf[3],
                              vs_u + kvrow * (QST2 * 2) + dbyte);
                MMA_F16(oacc[2*p],   af, vf[0], vf[2]);
                MMA_F16(oacc[2*p+1], af, vf[1], vf[3]);
            }
        }
    }

    // write O (fp16) rows q0+wid*16+(lane>>2), +8
    float inv0 = 1.0f / l0, inv1 = 1.0f / l1;
    int qrow = q0 + wid * 16 + (lane >> 2);
    __half* ob  = out + ((size_t)(b * NN + qrow)) * CB + h * 64 + (lane & 3) * 2;
    __half* ob2 = ob + 8 * CB;
    #pragma unroll
    for (int u = 0; u < 8; u++) {
        *reinterpret_cast<uint32_t*>(ob + u * 8)  = pack_h2(oacc[u][0] * inv0, oacc[u][1] * inv0);
        *reinterpret_cast<uint32_t*>(ob2 + u * 8) = pack_h2(oacc[u][2] * inv1, oacc[u][3] * inv1);
    }
}

// ---------------- launch ----------------
extern "C" void kernel_launch(void* const* d_in, const int* in_sizes, int n_in,
                              void* d_out, int out_size)
{
    const float* x     = (const float*)d_in[0];
    const float* Wqkv  = (const float*)d_in[1];
    const float* bqkv  = (const float*)d_in[2];
    const float* Wproj = (const float*)d_in[3];
    const float* bproj = (const float*)d_in[4];
    const float* g1    = (const float*)d_in[5];
    const float* b1    = (const float*)d_in[6];
    const float* g2    = (const float*)d_in[7];
    const float* b2    = (const float*)d_in[8];
    const float* W1    = (const float*)d_in[9];
    const float* bf1   = (const float*)d_in[10];
    const float* W2    = (const float*)d_in[11];
    const float* bf2   = (const float*)d_in[12];
    float* out = (float*)d_out;

    __half *hbuf, *qkvbuf, *attbuf, *h2buf, *ffbuf;
    __half *wqkvT, *wprojT, *w1T, *w2T;
    float *x2buf;
    cudaGetSymbolAddress((void**)&hbuf,   g_h);
    cudaGetSymbolAddress((void**)&qkvbuf, g_qkv);
    cudaGetSymbolAddress((void**)&attbuf, g_att);
    cudaGetSymbolAddress((void**)&x2buf,  g_x2);
    cudaGetSymbolAddress((void**)&h2buf,  g_h2);
    cudaGetSymbolAddress((void**)&ffbuf,  g_ff);
    cudaGetSymbolAddress((void**)&wqkvT,  g_wqkvT);
    cudaGetSymbolAddress((void**)&wprojT, g_wprojT);
    cudaGetSymbolAddress((void**)&w1T,    g_w1T);
    cudaGetSymbolAddress((void**)&w2T,    g_w2T);

    cudaFuncSetAttribute(attn_mma_kernel, cudaFuncAttributeMaxDynamicSharedMemorySize, ATT_SMEM);
    cudaFuncSetAttribute(mma_gemm<false, false, __half>, cudaFuncAttributeMaxDynamicSharedMemorySize, GSMEM);
    cudaFuncSetAttribute(mma_gemm<false, true,  float >, cudaFuncAttributeMaxDynamicSharedMemorySize, GSMEM);
    cudaFuncSetAttribute(mma_gemm<true,  false, __half>, cudaFuncAttributeMaxDynamicSharedMemorySize, GSMEM);

    // weight transposes (fp32 -> fp16 [N,K])
    transpose_h_kernel<<<dim3(3 * CB / 32, CB / 32), 256>>>(Wqkv,  wqkvT,  CB, 3 * CB);
    transpose_h_kernel<<<dim3(CB / 32, CB / 32), 256>>>(Wproj, wprojT, CB, CB);
    transpose_h_kernel<<<dim3(4 * CB / 32, CB / 32), 256>>>(W1, w1T, CB, 4 * CB);
    transpose_h_kernel<<<dim3(CB / 32, 4 * CB / 32), 256>>>(W2, w2T, 4 * CB, CB);

    // 1. LN1 -> fp16
    ln_kernel<<<MTOK, 256>>>(x, g1, b1, hbuf);
    // 2. qkv = h @ Wqkv + bqkv  -> fp16
    mma_gemm<false, false, __half><<<dim3(3 * CB / 128, MTOK / 128), 256, GSMEM>>>(
        hbuf, wqkvT, bqkv, nullptr, qkvbuf, MTOK, 3 * CB, CB);
    // 3. attention -> fp16
    attn_mma_kernel<<<dim3(NN / 128, BB * HH), 256, ATT_SMEM>>>(qkvbuf, attbuf);
    // 4. x2 = att @ Wproj + bproj + x  -> fp32
    mma_gemm<false, true, float><<<dim3(CB / 128, MTOK / 128), 256, GSMEM>>>(
        attbuf, wprojT, bproj, x, x2buf, MTOK, CB, CB);
    // 5. LN2 -> fp16
    ln_kernel<<<MTOK, 256>>>(x2buf, g2, b2, h2buf);
    // 6. ff = gelu(h2 @ W1 + bf1) -> fp16
    mma_gemm<true, false, __half><<<dim3(4 * CB / 128, MTOK / 128), 256, GSMEM>>>(
        h2buf, w1T, bf1, nullptr, ffbuf, MTOK, 4 * CB, CB);
    // 7. out = ff @ W2 + bf2 + x2  -> fp32
    mma_gemm<false, true, float><<<dim3(CB / 128, MTOK / 128), 256, GSMEM>>>(
        ffbuf, w2T, bf2, x2buf, out, MTOK, CB, 4 * CB);
}